// round 4
// baseline (speedup 1.0000x reference)
#include <cuda_runtime.h>
#include <math.h>
#include <stdint.h>

#define BB   8
#define LL   1024
#define HHN  8
#define DDIM 64
#define NQV  4
#define BHN  (BB*HHN)
#define CTX_ELEMS (BB*LL*HHN*DDIM)
#define PI_F 3.14159274101257324f

// Karatsuba-packed tf32-split operand buffers
// g_qA: [bh][l][96] = [qr_hi16 | qi_hi16 | qs_hi16 | qr_lo16 | qi_lo16 | qs_lo16], qs=qr+qi
// g_kB: [bh][s][96] = [kr_hi16 | ki_hi16 | ks_hi16 | kr_lo16 | ki_lo16 | ks_lo16], ks=kr-ki
__device__ float g_qA[(size_t)BHN * 1024 * 96];
__device__ float g_kB[(size_t)BHN * 1024 * 96];
// g_vS: [bh][s][128] = [v_hi(64) | v_lo(64)]
__device__ float g_vS[(size_t)BHN * 1024 * 128];

// ---------------- helpers ----------------
__device__ __forceinline__ void tsplit(float x, float& hi, float& lo) {
    uint32_t hb; asm("cvt.rna.tf32.f32 %0, %1;" : "=r"(hb) : "f"(x));
    hi = __uint_as_float(hb);
    float l = x - hi;
    uint32_t lb; asm("cvt.rna.tf32.f32 %0, %1;" : "=r"(lb) : "f"(l));
    lo = __uint_as_float(lb);
}
__device__ __forceinline__ void mma_tf32(float4& c, const uint32_t a[4],
                                         uint32_t b0, uint32_t b1) {
    asm("mma.sync.aligned.m16n8k8.row.col.f32.tf32.tf32.f32 "
        "{%0,%1,%2,%3},{%4,%5,%6,%7},{%8,%9},{%0,%1,%2,%3};"
        : "+f"(c.x), "+f"(c.y), "+f"(c.z), "+f"(c.w)
        : "r"(a[0]), "r"(a[1]), "r"(a[2]), "r"(a[3]), "r"(b0), "r"(b1));
}
__device__ __forceinline__ void cpa16(void* smem_dst, const void* gsrc) {
    uint32_t s = (uint32_t)__cvta_generic_to_shared(smem_dst);
    asm volatile("cp.async.cg.shared.global [%0], [%1], 16;" :: "r"(s), "l"(gsrc));
}
__device__ __forceinline__ void cpa_wait() {
    asm volatile("cp.async.commit_group;\ncp.async.wait_group 0;" ::: "memory");
}

// ======================================================================
// Prep: encode Q (blocks 0..255), encode K (256..511), V split (512..767)
// ======================================================================
__global__ void __launch_bounds__(256) prep_kernel(
    const float* __restrict__ qin, const float* __restrict__ kin,
    const float* __restrict__ vin,
    const float* __restrict__ wq, const float* __restrict__ bq,
    const float* __restrict__ wk, const float* __restrict__ bk)
{
    __shared__ float sw[NQV * DDIM];
    __shared__ float sb[NQV];
    const int bid = blockIdx.x;
    const int tid = threadIdx.x;

    if (bid >= 512) {   // ---- V split ----
        int n = (bid - 512) * 256 + tid;     // bh*1024 + s
        int bh = n >> 10, s = n & 1023;
        int b = bh >> 3, h = bh & 7;
        const float* src = vin + (size_t)((b * 1024 + s) * HHN + h) * DDIM;
        float* dst = g_vS + (size_t)n * 128;
#pragma unroll 8
        for (int d = 0; d < 64; d++) {
            float hi, lo; tsplit(src[d], hi, lo);
            dst[d] = hi; dst[64 + d] = lo;
        }
        return;
    }

    const int isK = (bid >= 256);
    const float* x = isK ? kin : qin;
    const float* w = isK ? wk : wq;
    const float* bias = isK ? bk : bq;
    if (tid < NQV * DDIM) sw[tid] = w[tid];
    if (tid < NQV) sb[tid] = bias[tid];
    __syncthreads();

    int n  = (bid & 255) * 256 + tid;        // bh*1024 + pos
    int bh = n >> 10, loc = n & 1023;
    int b = bh >> 3, h = bh & 7;
    const float* xr = x + (size_t)((b * 1024 + loc) * HHN + h) * DDIM;

    float th[NQV];
#pragma unroll
    for (int j = 0; j < NQV; j++) th[j] = sb[j];
#pragma unroll 4
    for (int d = 0; d < DDIM; d += 4) {
        float4 xv = *(const float4*)(xr + d);
#pragma unroll
        for (int j = 0; j < NQV; j++) {
            th[j] += xv.x * sw[j * DDIM + d]     + xv.y * sw[j * DDIM + d + 1]
                   + xv.z * sw[j * DDIM + d + 2] + xv.w * sw[j * DDIM + d + 3];
        }
    }
#pragma unroll
    for (int j = 0; j < NQV; j++) th[j] = tanhf(th[j]) * PI_F;
    float bt[3];
#pragma unroll
    for (int p = 0; p < 3; p++) bt[p] = th[p] * th[p + 1];

    float co[16], si[16];
#pragma unroll
    for (int d = 0; d < 16; d++) {
        float a = 0.f;
        a += ((d >> 3) & 1) ? -th[0] : th[0];
        a += ((d >> 2) & 1) ? -th[1] : th[1];
        a += ((d >> 1) & 1) ? -th[2] : th[2];
        a += ( d       & 1) ? -th[3] : th[3];
        a += (((d >> 3) ^ (d >> 2)) & 1) ? -bt[0] : bt[0];
        a += (((d >> 2) ^ (d >> 1)) & 1) ? -bt[1] : bt[1];
        a += (((d >> 1) ^  d      ) & 1) ? -bt[2] : bt[2];
        sincosf(-0.5f * a, &si[d], &co[d]);
    }
    float re[16], im[16];
#pragma unroll
    for (int d = 0; d < 16; d++) { re[d] = co[d]; im[d] = si[d]; }
#pragma unroll
    for (int hs = 1; hs < 16; hs <<= 1) {
#pragma unroll
        for (int i = 0; i < 16; i++) {
            if ((i & hs) == 0) {
                int j2 = i | hs;
                float ar = re[i], ai = im[i], br = re[j2], bi = im[j2];
                re[i] = ar + br;  im[i] = ai + bi;
                re[j2] = ar - br; im[j2] = ai - bi;
            }
        }
    }

    float* o = (isK ? g_kB : g_qA) + (size_t)n * 96;
#pragma unroll
    for (int jg = 0; jg < 4; jg++) {        // 4 dims at a time -> 6 float4 stores
        float4 rhi, ihi, shi, rlo, ilo, slo;
        float* prh = &rhi.x; float* pih = &ihi.x; float* psh = &shi.x;
        float* prl = &rlo.x; float* pil = &ilo.x; float* psl = &slo.x;
#pragma unroll
        for (int jj = 0; jj < 4; jj++) {
            int d = jg * 4 + jj;
            float tr = re[d] * 0.0625f, ti = im[d] * 0.0625f;
            float vr = tr * co[d] - ti * si[d];
            float vi = tr * si[d] + ti * co[d];
            float vs = isK ? (vr - vi) : (vr + vi);
            float hi, lo;
            tsplit(vr, hi, lo); prh[jj] = hi; prl[jj] = lo;
            tsplit(vi, hi, lo); pih[jj] = hi; pil[jj] = lo;
            tsplit(vs, hi, lo); psh[jj] = hi; psl[jj] = lo;
        }
        float4* o4 = (float4*)o;
        o4[jg]      = rhi;  o4[4 + jg]  = ihi;  o4[8 + jg]  = shi;
        o4[12 + jg] = rlo;  o4[16 + jg] = ilo;  o4[20 + jg] = slo;
    }
}

// ======================================================================
// Fused attention: per (bh, 32-l tile)
//  A: Karatsuba 3xTF32 scores -> smem raw + register rowsums
//  B: normalized weights streamed out (single DRAM pass)
//  C: context = (raw @ Vsplit) * inv, 3xTF32
// ======================================================================
#define SCROW 1044
#define OFF_CHK (32 * SCROW)                    // 33408 floats
#define SMEM_FLOATS (OFF_CHK + 17408)           // + chunk area (max 128x136)
#define SMEM_BYTES (SMEM_FLOATS * 4)            // 203264

__global__ void __launch_bounds__(256, 1) attn_fused(float* __restrict__ out)
{
    extern __shared__ float sm[];
    float* sc  = sm;                 // [32][1044] raw scores
    float* chk = sm + OFF_CHK;       // K chunk [128][100] / V chunk [128][136]
    __shared__ float sred[4][32];
    __shared__ float sinv[32];

    const int bh = blockIdx.y;
    const int l0 = blockIdx.x * 32;
    const int b = bh >> 3, h = bh & 7;
    const int tid = threadIdx.x;
    const int w = tid >> 5, lane = tid & 31;
    const int gr = lane >> 2, ctg = lane & 3;

    // ---- phase A: warp = (mtA in 0..1, sh in 0..3) ----
    const int mtA = w & 1, sh = w >> 1;

    // resident A fragments: 3 gemms x 2 k-steps, hi+lo
    uint32_t ah[3][2][4], al[3][2][4];
    {
        const float* qa = g_qA + (size_t)bh * 98304 + (size_t)(l0 + mtA * 16) * 96;
#pragma unroll
        for (int g = 0; g < 3; g++)
#pragma unroll
            for (int kk = 0; kk < 2; kk++) {
                int c0 = g * 16 + kk * 8 + ctg;
                ah[g][kk][0] = __float_as_uint(qa[gr * 96 + c0]);
                ah[g][kk][1] = __float_as_uint(qa[(gr + 8) * 96 + c0]);
                ah[g][kk][2] = __float_as_uint(qa[gr * 96 + c0 + 4]);
                ah[g][kk][3] = __float_as_uint(qa[(gr + 8) * 96 + c0 + 4]);
                al[g][kk][0] = __float_as_uint(qa[gr * 96 + 48 + c0]);
                al[g][kk][1] = __float_as_uint(qa[(gr + 8) * 96 + 48 + c0]);
                al[g][kk][2] = __float_as_uint(qa[gr * 96 + 48 + c0 + 4]);
                al[g][kk][3] = __float_as_uint(qa[(gr + 8) * 96 + 48 + c0 + 4]);
            }
    }

    const float* kg = g_kB + (size_t)bh * 98304;
    float rs0 = 0.f, rs1 = 0.f;

    for (int ch = 0; ch < 8; ch++) {
        __syncthreads();
        // stage K chunk: 128 rows x 24 float4 -> [128][100] padded
        for (int i = tid; i < 3072; i += 256) {
            int s = i / 24, c4 = i % 24;
            cpa16(&chk[s * 100 + c4 * 4], kg + (size_t)(ch * 128 + s) * 96 + c4 * 4);
        }
        cpa_wait();
        __syncthreads();

        float4 acc[4][3];
#pragma unroll
        for (int nt = 0; nt < 4; nt++)
#pragma unroll
            for (int g = 0; g < 3; g++) acc[nt][g] = make_float4(0.f, 0.f, 0.f, 0.f);

        const float* bb = &chk[(sh * 32 + gr) * 100];
#pragma unroll
        for (int kk = 0; kk < 2; kk++)
#pragma unroll
            for (int g = 0; g < 3; g++) {
                int c0 = g * 16 + kk * 8 + ctg;
#pragma unroll
                for (int nt = 0; nt < 4; nt++) {
                    const float* bc = bb + nt * 800;
                    uint32_t b0 = __float_as_uint(bc[c0]);
                    uint32_t b1 = __float_as_uint(bc[c0 + 4]);
                    uint32_t q0 = __float_as_uint(bc[48 + c0]);
                    uint32_t q1 = __float_as_uint(bc[48 + c0 + 4]);
                    mma_tf32(acc[nt][g], ah[g][kk], b0, b1);
                    mma_tf32(acc[nt][g], ah[g][kk], q0, q1);
                    mma_tf32(acc[nt][g], al[g][kk], b0, b1);
                }
            }

        // epilogue: fid_r = t1+t2, fid_i = t3-t1+t2; raw score = fr^2+fi^2
        const int rt = mtA * 16 + gr, rb = rt + 8;
#pragma unroll
        for (int nt = 0; nt < 4; nt++) {
            float4 c1 = acc[nt][0], c2 = acc[nt][1], c3 = acc[nt][2];
            float fr, fi, p0, p1, p2, p3;
            fr = c1.x + c2.x; fi = c3.x - c1.x + c2.x; p0 = fr * fr + fi * fi;
            fr = c1.y + c2.y; fi = c3.y - c1.y + c2.y; p1 = fr * fr + fi * fi;
            fr = c1.z + c2.z; fi = c3.z - c1.z + c2.z; p2 = fr * fr + fi * fi;
            fr = c1.w + c2.w; fi = c3.w - c1.w + c2.w; p3 = fr * fr + fi * fi;
            int col = ch * 128 + sh * 32 + nt * 8 + 2 * ctg;
            *(float2*)&sc[rt * SCROW + col] = make_float2(p0, p1);
            *(float2*)&sc[rb * SCROW + col] = make_float2(p2, p3);
            rs0 += p0 + p1; rs1 += p2 + p3;
        }
    }

    // rowsum reduce over ctg, stash per-(quarter) partials
    rs0 += __shfl_xor_sync(0xFFFFFFFFu, rs0, 1);
    rs0 += __shfl_xor_sync(0xFFFFFFFFu, rs0, 2);
    rs1 += __shfl_xor_sync(0xFFFFFFFFu, rs1, 1);
    rs1 += __shfl_xor_sync(0xFFFFFFFFu, rs1, 2);
    if (ctg == 0) {
        sred[sh][mtA * 16 + gr] = rs0;
        sred[sh][mtA * 16 + gr + 8] = rs1;
    }
    __syncthreads();
    if (tid < 32)
        sinv[tid] = 1.0f / (sred[0][tid] + sred[1][tid] + sred[2][tid] + sred[3][tid] + 1e-6f);
    __syncthreads();

    // ---- phase B: normalized weights, single DRAM pass ----
    {
        float4* wout = (float4*)(out + (size_t)CTX_ELEMS + ((size_t)bh * 1024 + l0) * 1024);
#pragma unroll 4
        for (int i = tid; i < 32 * 256; i += 256) {
            int l = i >> 8, f4 = i & 255;
            float4 v = *(const float4*)&sc[l * SCROW + f4 * 4];
            float iv = sinv[l];
            v.x *= iv; v.y *= iv; v.z *= iv; v.w *= iv;
            wout[(size_t)l * 256 + f4] = v;
        }
    }

    // ---- phase C: context. warp = (mtC in 0..1, dq in 0..3) ----
    const int mtC = w & 1, dq = w >> 1;
    float4 cacc[2];
    cacc[0] = make_float4(0.f, 0.f, 0.f, 0.f);
    cacc[1] = make_float4(0.f, 0.f, 0.f, 0.f);

    const float4* vg = (const float4*)(g_vS + (size_t)bh * 131072);
    for (int ch = 0; ch < 8; ch++) {
        __syncthreads();
        for (int i = tid; i < 4096; i += 256) {   // V chunk 128 x [hi64|lo64] -> [128][136]
            int s = i >> 5, f4 = i & 31;
            int dst = s * 136 + (f4 < 16 ? f4 * 4 : 68 + (f4 - 16) * 4);
            cpa16(&chk[dst], vg + (size_t)(ch * 128 + s) * 32 + f4);
        }
        cpa_wait();
        __syncthreads();

#pragma unroll 2
        for (int kk = 0; kk < 16; kk++) {
            int scol = ch * 128 + kk * 8;
            uint32_t ahh[4], all2[4];
            float hi, lo;
            tsplit(sc[(mtC * 16 + gr) * SCROW + scol + ctg], hi, lo);
            ahh[0] = __float_as_uint(hi); all2[0] = __float_as_uint(lo);
            tsplit(sc[(mtC * 16 + gr + 8) * SCROW + scol + ctg], hi, lo);
            ahh[1] = __float_as_uint(hi); all2[1] = __float_as_uint(lo);
            tsplit(sc[(mtC * 16 + gr) * SCROW + scol + ctg + 4], hi, lo);
            ahh[2] = __float_as_uint(hi); all2[2] = __float_as_uint(lo);
            tsplit(sc[(mtC * 16 + gr + 8) * SCROW + scol + ctg + 4], hi, lo);
            ahh[3] = __float_as_uint(hi); all2[3] = __float_as_uint(lo);

            const float* vr0 = &chk[(kk * 8 + ctg) * 136];
            const float* vr1 = &chk[(kk * 8 + ctg + 4) * 136];
#pragma unroll
            for (int nt = 0; nt < 2; nt++) {
                int d0 = dq * 16 + nt * 8 + gr;
                uint32_t b0 = __float_as_uint(vr0[d0]);
                uint32_t b1 = __float_as_uint(vr1[d0]);
                uint32_t q0 = __float_as_uint(vr0[68 + d0]);
                uint32_t q1 = __float_as_uint(vr1[68 + d0]);
                mma_tf32(cacc[nt], ahh, b0, b1);
                mma_tf32(cacc[nt], all2, b0, b1);
                mma_tf32(cacc[nt], ahh, q0, q1);
            }
        }
    }

    {
        float ivt = sinv[mtC * 16 + gr], ivb = sinv[mtC * 16 + gr + 8];
        int lt = l0 + mtC * 16 + gr, lb = lt + 8;
#pragma unroll
        for (int nt = 0; nt < 2; nt++) {
            int d = dq * 16 + nt * 8 + 2 * ctg;
            *(float2*)&out[((size_t)(b * 1024 + lt) * 8 + h) * 64 + d]
                = make_float2(cacc[nt].x * ivt, cacc[nt].y * ivt);
            *(float2*)&out[((size_t)(b * 1024 + lb) * 8 + h) * 64 + d]
                = make_float2(cacc[nt].z * ivb, cacc[nt].w * ivb);
        }
    }
}

// ======================================================================
extern "C" void kernel_launch(void* const* d_in, const int* in_sizes, int n_in,
                              void* d_out, int out_size)
{
    (void)in_sizes; (void)n_in; (void)out_size;
    const float* q  = (const float*)d_in[0];
    const float* k  = (const float*)d_in[1];
    const float* v  = (const float*)d_in[2];
    const float* wq = (const float*)d_in[3];
    const float* bq = (const float*)d_in[4];
    const float* wk = (const float*)d_in[5];
    const float* bk = (const float*)d_in[6];
    float* out = (float*)d_out;

    cudaFuncSetAttribute(attn_fused, cudaFuncAttributeMaxDynamicSharedMemorySize, SMEM_BYTES);

    prep_kernel<<<768, 256>>>(q, k, v, wq, bq, wk, bk);
    attn_fused<<<dim3(32, BHN), 256, SMEM_BYTES>>>(out);
}

// round 5
// speedup vs baseline: 1.3677x; 1.3677x over previous
#include <cuda_runtime.h>
#include <cuda_bf16.h>
#include <math.h>
#include <stdint.h>

#define BB   8
#define LL   1024
#define HHN  8
#define DDIM 64
#define NQV  4
#define BHN  (BB*HHN)
#define CTX_ELEMS (BB*LL*HHN*DDIM)
#define PI_F 3.14159274101257324f

// Karatsuba tf32-split Q/K: [bh][pos][96] = [r_hi16|i_hi16|s_hi16|r_lo16|i_lo16|s_lo16]
__device__ float g_qA[(size_t)BHN * 1024 * 96];
__device__ float g_kB[(size_t)BHN * 1024 * 96];
// V transposed bf16 split: [bh][t=hi/lo][d 64][s 1024]
__device__ __nv_bfloat16 g_vT[(size_t)BHN * 2 * 64 * 1024];

// ---------------- helpers ----------------
__device__ __forceinline__ void tsplit(float x, float& hi, float& lo) {
    uint32_t hb; asm("cvt.rna.tf32.f32 %0, %1;" : "=r"(hb) : "f"(x));
    hi = __uint_as_float(hb);
    float l = x - hi;
    uint32_t lb; asm("cvt.rna.tf32.f32 %0, %1;" : "=r"(lb) : "f"(l));
    lo = __uint_as_float(lb);
}
__device__ __forceinline__ void mma_tf32(float4& c, const uint32_t a[4],
                                         uint32_t b0, uint32_t b1) {
    asm("mma.sync.aligned.m16n8k8.row.col.f32.tf32.tf32.f32 "
        "{%0,%1,%2,%3},{%4,%5,%6,%7},{%8,%9},{%0,%1,%2,%3};"
        : "+f"(c.x), "+f"(c.y), "+f"(c.z), "+f"(c.w)
        : "r"(a[0]), "r"(a[1]), "r"(a[2]), "r"(a[3]), "r"(b0), "r"(b1));
}
__device__ __forceinline__ void mma_bf16(float4& c, const uint32_t a[4],
                                         uint32_t b0, uint32_t b1) {
    asm("mma.sync.aligned.m16n8k16.row.col.f32.bf16.bf16.f32 "
        "{%0,%1,%2,%3},{%4,%5,%6,%7},{%8,%9},{%0,%1,%2,%3};"
        : "+f"(c.x), "+f"(c.y), "+f"(c.z), "+f"(c.w)
        : "r"(a[0]), "r"(a[1]), "r"(a[2]), "r"(a[3]), "r"(b0), "r"(b1));
}
// pack (a -> low bf16, b -> high bf16)
__device__ __forceinline__ uint32_t bfpack(float a, float b) {
    uint32_t r; asm("cvt.rn.bf16x2.f32 %0, %1, %2;" : "=r"(r) : "f"(b), "f"(a)); return r;
}
__device__ __forceinline__ float bflowf(uint32_t v)  { return __uint_as_float(v << 16); }
__device__ __forceinline__ float bfhighf(uint32_t v) { return __uint_as_float(v & 0xFFFF0000u); }
__device__ __forceinline__ void cpa16(void* smem_dst, const void* gsrc) {
    uint32_t s = (uint32_t)__cvta_generic_to_shared(smem_dst);
    asm volatile("cp.async.cg.shared.global [%0], [%1], 16;" :: "r"(s), "l"(gsrc));
}
__device__ __forceinline__ void cpa_wait() {
    asm volatile("cp.async.commit_group;\ncp.async.wait_group 0;" ::: "memory");
}

// ======================================================================
// Prep: Q encode (0..255), K encode (256..511), V transpose+split (512..767)
// ======================================================================
#define PREP_SMEM (2 * 64 * 264 * 2)    // 67584 B for V transpose
__global__ void __launch_bounds__(256) prep_kernel(
    const float* __restrict__ qin, const float* __restrict__ kin,
    const float* __restrict__ vin,
    const float* __restrict__ wq, const float* __restrict__ bq,
    const float* __restrict__ wk, const float* __restrict__ bk)
{
    extern __shared__ __nv_bfloat16 dynsm[];
    __shared__ float sw[NQV * DDIM];
    __shared__ float sb[NQV];
    const int bid = blockIdx.x;
    const int tid = threadIdx.x;

    if (bid >= 512) {   // ---- V transpose + bf16 split ----
        int vb = bid - 512;              // 0..255
        int bh = vb >> 2, sc0 = (vb & 3) * 256;
        int b = bh >> 3, h = bh & 7;
        const float4* vg = (const float4*)vin;
        __nv_bfloat16* smA = dynsm;      // [128 rows (hi64|lo64)][264]
#pragma unroll
        for (int j = 0; j < 16; j++) {
            int i = tid + j * 256;
            int s = i >> 4, d4 = i & 15;
            float4 xv = vg[((size_t)((b * 1024 + sc0 + s) * 8 + h)) * 16 + d4];
            const float* px = &xv.x;
#pragma unroll
            for (int jj = 0; jj < 4; jj++) {
                int d = d4 * 4 + jj;
                float val = px[jj];
                __nv_bfloat16 hb = __float2bfloat16(val);
                float rr = val - __bfloat162float(hb);
                smA[d * 264 + s] = hb;
                smA[(64 + d) * 264 + s] = __float2bfloat16(rr);
            }
        }
        __syncthreads();
        __nv_bfloat16* dst = g_vT + (size_t)bh * 131072;
#pragma unroll
        for (int j = 0; j < 16; j++) {
            int i = tid + j * 256;
            int row = i >> 5, c = i & 31;
            float4 v4 = *(const float4*)&smA[row * 264 + c * 8];
            *(float4*)&dst[(size_t)row * 1024 + sc0 + c * 8] = v4;
        }
        return;
    }

    const int isK = (bid >= 256);
    const float* x = isK ? kin : qin;
    const float* w = isK ? wk : wq;
    const float* bias = isK ? bk : bq;
    if (tid < NQV * DDIM) sw[tid] = w[tid];
    if (tid < NQV) sb[tid] = bias[tid];
    __syncthreads();

    int n  = (bid & 255) * 256 + tid;
    int bh = n >> 10, loc = n & 1023;
    int b = bh >> 3, h = bh & 7;
    const float* xr = x + (size_t)((b * 1024 + loc) * HHN + h) * DDIM;

    float th[NQV];
#pragma unroll
    for (int j = 0; j < NQV; j++) th[j] = sb[j];
#pragma unroll 4
    for (int d = 0; d < DDIM; d += 4) {
        float4 xv = *(const float4*)(xr + d);
#pragma unroll
        for (int j = 0; j < NQV; j++) {
            th[j] += xv.x * sw[j * DDIM + d]     + xv.y * sw[j * DDIM + d + 1]
                   + xv.z * sw[j * DDIM + d + 2] + xv.w * sw[j * DDIM + d + 3];
        }
    }
#pragma unroll
    for (int j = 0; j < NQV; j++) th[j] = tanhf(th[j]) * PI_F;
    float bt[3];
#pragma unroll
    for (int p = 0; p < 3; p++) bt[p] = th[p] * th[p + 1];

    float co[16], si[16];
#pragma unroll
    for (int d = 0; d < 16; d++) {
        float a = 0.f;
        a += ((d >> 3) & 1) ? -th[0] : th[0];
        a += ((d >> 2) & 1) ? -th[1] : th[1];
        a += ((d >> 1) & 1) ? -th[2] : th[2];
        a += ( d       & 1) ? -th[3] : th[3];
        a += (((d >> 3) ^ (d >> 2)) & 1) ? -bt[0] : bt[0];
        a += (((d >> 2) ^ (d >> 1)) & 1) ? -bt[1] : bt[1];
        a += (((d >> 1) ^  d      ) & 1) ? -bt[2] : bt[2];
        sincosf(-0.5f * a, &si[d], &co[d]);
    }
    float re[16], im[16];
#pragma unroll
    for (int d = 0; d < 16; d++) { re[d] = co[d]; im[d] = si[d]; }
#pragma unroll
    for (int hs = 1; hs < 16; hs <<= 1) {
#pragma unroll
        for (int i = 0; i < 16; i++) {
            if ((i & hs) == 0) {
                int j2 = i | hs;
                float ar = re[i], ai = im[i], br = re[j2], bi = im[j2];
                re[i] = ar + br;  im[i] = ai + bi;
                re[j2] = ar - br; im[j2] = ai - bi;
            }
        }
    }

    float* o = (isK ? g_kB : g_qA) + (size_t)n * 96;
#pragma unroll
    for (int jg = 0; jg < 4; jg++) {
        float4 rhi, ihi, shi, rlo, ilo, slo;
        float* prh = &rhi.x; float* pih = &ihi.x; float* psh = &shi.x;
        float* prl = &rlo.x; float* pil = &ilo.x; float* psl = &slo.x;
#pragma unroll
        for (int jj = 0; jj < 4; jj++) {
            int d = jg * 4 + jj;
            float tr = re[d] * 0.0625f, ti = im[d] * 0.0625f;
            float vr = tr * co[d] - ti * si[d];
            float vi = tr * si[d] + ti * co[d];
            float vs = isK ? (vr - vi) : (vr + vi);
            float hi, lo;
            tsplit(vr, hi, lo); prh[jj] = hi; prl[jj] = lo;
            tsplit(vi, hi, lo); pih[jj] = hi; pil[jj] = lo;
            tsplit(vs, hi, lo); psh[jj] = hi; psl[jj] = lo;
        }
        float4* o4 = (float4*)o;
        o4[jg]      = rhi;  o4[4 + jg]  = ihi;  o4[8 + jg]  = shi;
        o4[12 + jg] = rhi.x == rhi.x ? rlo : rlo;  // keep layout explicit
        o4[12 + jg] = rlo;  o4[16 + jg] = ilo;  o4[20 + jg] = slo;
    }
}

// ======================================================================
// Fused attention: per (bh, 16-l tile), occ 2
//  A: tf32 Karatsuba scores -> packed bf16 hi/lo pairs in smem + rowsums
//  B: one normalized-weights DRAM pass (reconstruct hi+lo)
//  C: context = bf16 2-way split mma straight from packed smem
// ======================================================================
#define SCH 516                               // u32 stride per score row
#define SC_U32 (16 * SCH)                     // one array (hi or lo)
#define CHK_OFF (2 * SC_U32)                  // u32 offset of chunk area
#define SMEM_BYTES (CHK_OFF * 4 + 34816)      // 66048 + 34816 = 100864

__global__ void __launch_bounds__(256, 2) attn_fused(float* __restrict__ out)
{
    extern __shared__ uint32_t sm32[];
    uint32_t* scHi = sm32;
    uint32_t* scLo = sm32 + SC_U32;
    float*    chkf = (float*)(sm32 + CHK_OFF);
    uint32_t* chku = sm32 + CHK_OFF;
    __shared__ float sred[8][16];
    __shared__ float sinv[16];

    const int bh = blockIdx.y;
    const int l0 = blockIdx.x * 16;
    const int b = bh >> 3, h = bh & 7;
    const int tid = threadIdx.x;
    const int w = tid >> 5, lane = tid & 31;
    const int gr = lane >> 2, ctg = lane & 3;

    // resident tf32 Q fragments: 3 gemms x 2 ksteps, hi+lo
    uint32_t ah[3][2][4], al[3][2][4];
    {
        const float* qa = g_qA + (size_t)bh * 98304 + (size_t)l0 * 96;
#pragma unroll
        for (int g = 0; g < 3; g++)
#pragma unroll
            for (int kk = 0; kk < 2; kk++) {
                int c0 = g * 16 + kk * 8 + ctg;
                ah[g][kk][0] = __float_as_uint(qa[gr * 96 + c0]);
                ah[g][kk][1] = __float_as_uint(qa[(gr + 8) * 96 + c0]);
                ah[g][kk][2] = __float_as_uint(qa[gr * 96 + c0 + 4]);
                ah[g][kk][3] = __float_as_uint(qa[(gr + 8) * 96 + c0 + 4]);
                al[g][kk][0] = __float_as_uint(qa[gr * 96 + 48 + c0]);
                al[g][kk][1] = __float_as_uint(qa[(gr + 8) * 96 + 48 + c0]);
                al[g][kk][2] = __float_as_uint(qa[gr * 96 + 48 + c0 + 4]);
                al[g][kk][3] = __float_as_uint(qa[(gr + 8) * 96 + 48 + c0 + 4]);
            }
    }

    // ---- phase A: scores, 16 chunks of 64 s ----
    const float* kg = g_kB + (size_t)bh * 98304;
    float rs0 = 0.f, rs1 = 0.f;

    for (int ch = 0; ch < 16; ch++) {
        __syncthreads();
#pragma unroll
        for (int j = 0; j < 6; j++) {
            int i = tid + j * 256;
            int s = i / 24, c4 = i % 24;
            cpa16(&chkf[s * 100 + c4 * 4], kg + (size_t)(ch * 64 + s) * 96 + c4 * 4);
        }
        cpa_wait();
        __syncthreads();

        float4 acc[3];
#pragma unroll
        for (int g = 0; g < 3; g++) acc[g] = make_float4(0.f, 0.f, 0.f, 0.f);

        const float* bb = &chkf[(w * 8 + gr) * 100];
#pragma unroll
        for (int kk = 0; kk < 2; kk++)
#pragma unroll
            for (int g = 0; g < 3; g++) {
                int c0 = g * 16 + kk * 8 + ctg;
                uint32_t b0 = __float_as_uint(bb[c0]);
                uint32_t b1 = __float_as_uint(bb[c0 + 4]);
                uint32_t q0 = __float_as_uint(bb[48 + c0]);
                uint32_t q1 = __float_as_uint(bb[48 + c0 + 4]);
                mma_tf32(acc[g], ah[g][kk], b0, b1);
                mma_tf32(acc[g], ah[g][kk], q0, q1);
                mma_tf32(acc[g], al[g][kk], b0, b1);
            }

        // Karatsuba combine; raw score; split to packed bf16 hi/lo pairs
        float4 c1 = acc[0], c2 = acc[1], c3 = acc[2];
        float fr, fi, p0, p1, p2, p3;
        fr = c1.x + c2.x; fi = c3.x - c1.x + c2.x; p0 = fr * fr + fi * fi;
        fr = c1.y + c2.y; fi = c3.y - c1.y + c2.y; p1 = fr * fr + fi * fi;
        fr = c1.z + c2.z; fi = c3.z - c1.z + c2.z; p2 = fr * fr + fi * fi;
        fr = c1.w + c2.w; fi = c3.w - c1.w + c2.w; p3 = fr * fr + fi * fi;

        int pairIdx = ch * 32 + w * 4 + ctg;
        uint32_t h01 = bfpack(p0, p1);
        uint32_t h23 = bfpack(p2, p3);
        scHi[gr * SCH + pairIdx] = h01;
        scHi[(gr + 8) * SCH + pairIdx] = h23;
        scLo[gr * SCH + pairIdx] = bfpack(p0 - bflowf(h01), p1 - bfhighf(h01));
        scLo[(gr + 8) * SCH + pairIdx] = bfpack(p2 - bflowf(h23), p3 - bfhighf(h23));
        rs0 += p0 + p1; rs1 += p2 + p3;
    }

    // rowsums
    rs0 += __shfl_xor_sync(0xFFFFFFFFu, rs0, 1);
    rs0 += __shfl_xor_sync(0xFFFFFFFFu, rs0, 2);
    rs1 += __shfl_xor_sync(0xFFFFFFFFu, rs1, 1);
    rs1 += __shfl_xor_sync(0xFFFFFFFFu, rs1, 2);
    if (ctg == 0) { sred[w][gr] = rs0; sred[w][gr + 8] = rs1; }
    __syncthreads();

    // prefetch V chunk 0 while phase B runs
    const __nv_bfloat16* vt = g_vT + (size_t)bh * 131072;
#pragma unroll
    for (int j = 0; j < 8; j++) {
        int i = tid + j * 256;
        int row = i >> 4, f = i & 15;
        cpa16(&chku[row * 68 + f * 4], vt + (size_t)row * 1024 + f * 8);
    }
    if (tid < 16) {
        float s = 0.f;
#pragma unroll
        for (int ww = 0; ww < 8; ww++) s += sred[ww][tid];
        sinv[tid] = 1.0f / (s + 1e-6f);
    }
    __syncthreads();

    // ---- phase B: single normalized weights pass ----
    {
        float2* wout = (float2*)(out + (size_t)CTX_ELEMS + ((size_t)bh * 1024 + l0) * 1024);
#pragma unroll 8
        for (int i = tid; i < 8192; i += 256) {
            int row = i >> 9, pr = i & 511;
            uint32_t hv = scHi[row * SCH + pr];
            uint32_t lv = scLo[row * SCH + pr];
            float iv = sinv[row];
            float w0 = (bflowf(hv) + bflowf(lv)) * iv;
            float w1 = (bfhighf(hv) + bfhighf(lv)) * iv;
            wout[(size_t)row * 512 + pr] = make_float2(w0, w1);
        }
    }
    cpa_wait();
    __syncthreads();

    // ---- phase C: context, warp = d-octet dq=w ----
    const int dq = w;
    float4 aHH = make_float4(0.f, 0.f, 0.f, 0.f);
    float4 aHL = make_float4(0.f, 0.f, 0.f, 0.f);
    float4 aLH = make_float4(0.f, 0.f, 0.f, 0.f);
    const int vrowH = dq * 8 + gr;         // V hi row (d)
    const int vrowL = 64 + vrowH;          // V lo row

    for (int ch = 0; ch < 8; ch++) {
        if (ch > 0) {
            __syncthreads();
#pragma unroll
            for (int j = 0; j < 8; j++) {
                int i = tid + j * 256;
                int row = i >> 4, f = i & 15;
                cpa16(&chku[row * 68 + f * 4],
                      vt + (size_t)row * 1024 + ch * 128 + f * 8);
            }
            cpa_wait();
            __syncthreads();
        }
#pragma unroll
        for (int kk = 0; kk < 8; kk++) {
            int pb = ch * 64 + kk * 8;
            uint32_t aH[4], aL[4];
            aH[0] = scHi[gr * SCH + pb + ctg];
            aH[1] = scHi[(gr + 8) * SCH + pb + ctg];
            aH[2] = scHi[gr * SCH + pb + 4 + ctg];
            aH[3] = scHi[(gr + 8) * SCH + pb + 4 + ctg];
            aL[0] = scLo[gr * SCH + pb + ctg];
            aL[1] = scLo[(gr + 8) * SCH + pb + ctg];
            aL[2] = scLo[gr * SCH + pb + 4 + ctg];
            aL[3] = scLo[(gr + 8) * SCH + pb + 4 + ctg];

            uint32_t bh0 = chku[vrowH * 68 + kk * 8 + ctg];
            uint32_t bh1 = chku[vrowH * 68 + kk * 8 + 4 + ctg];
            uint32_t bl0 = chku[vrowL * 68 + kk * 8 + ctg];
            uint32_t bl1 = chku[vrowL * 68 + kk * 8 + 4 + ctg];

            mma_bf16(aHH, aH, bh0, bh1);
            mma_bf16(aHL, aH, bl0, bl1);
            mma_bf16(aLH, aL, bh0, bh1);
        }
    }

    {
        float4 c = make_float4(aHH.x + aHL.x + aLH.x, aHH.y + aHL.y + aLH.y,
                               aHH.z + aHL.z + aLH.z, aHH.w + aHL.w + aLH.w);
        float ivt = sinv[gr], ivb = sinv[gr + 8];
        int lt = l0 + gr, lb = lt + 8;
        int d = dq * 8 + 2 * ctg;
        *(float2*)&out[((size_t)((b * 1024 + lt) * 8 + h)) * 64 + d]
            = make_float2(c.x * ivt, c.y * ivt);
        *(float2*)&out[((size_t)((b * 1024 + lb) * 8 + h)) * 64 + d]
            = make_float2(c.z * ivb, c.w * ivb);
    }
}

// ======================================================================
extern "C" void kernel_launch(void* const* d_in, const int* in_sizes, int n_in,
                              void* d_out, int out_size)
{
    (void)in_sizes; (void)n_in; (void)out_size;
    const float* q  = (const float*)d_in[0];
    const float* k  = (const float*)d_in[1];
    const float* v  = (const float*)d_in[2];
    const float* wq = (const float*)d_in[3];
    const float* bq = (const float*)d_in[4];
    const float* wk = (const float*)d_in[5];
    const float* bk = (const float*)d_in[6];
    float* out = (float*)d_out;

    cudaFuncSetAttribute(prep_kernel, cudaFuncAttributeMaxDynamicSharedMemorySize, PREP_SMEM);
    cudaFuncSetAttribute(attn_fused,  cudaFuncAttributeMaxDynamicSharedMemorySize, SMEM_BYTES);

    prep_kernel<<<768, 256, PREP_SMEM>>>(q, k, v, wq, bq, wk, bk);
    attn_fused<<<dim3(64, BHN), 256, SMEM_BYTES>>>(out);
}

// round 6
// speedup vs baseline: 1.8173x; 1.3288x over previous
#include <cuda_runtime.h>
#include <cuda_bf16.h>
#include <math.h>
#include <stdint.h>

#define BB   8
#define LL   1024
#define HHN  8
#define DDIM 64
#define NQV  4
#define BHN  (BB*HHN)
#define CTX_ELEMS (BB*LL*HHN*DDIM)
#define PI_F 3.14159274101257324f

// Karatsuba tf32-split Q/K: [bh][pos][96] = [r_hi16|i_hi16|s_hi16|r_lo16|i_lo16|s_lo16]
__device__ float g_qA[(size_t)BHN * 1024 * 96];
__device__ float g_kB[(size_t)BHN * 1024 * 96];
// V transposed bf16 split: [bh][hi d64 | lo d64][s 1024]
__device__ __nv_bfloat16 g_vT[(size_t)BHN * 2 * 64 * 1024];

// ---------------- helpers ----------------
__device__ __forceinline__ void tsplit(float x, float& hi, float& lo) {
    uint32_t hb; asm("cvt.rna.tf32.f32 %0, %1;" : "=r"(hb) : "f"(x));
    hi = __uint_as_float(hb);
    float l = x - hi;
    uint32_t lb; asm("cvt.rna.tf32.f32 %0, %1;" : "=r"(lb) : "f"(l));
    lo = __uint_as_float(lb);
}
__device__ __forceinline__ void mma_tf32(float4& c, const uint32_t a[4],
                                         uint32_t b0, uint32_t b1) {
    asm("mma.sync.aligned.m16n8k8.row.col.f32.tf32.tf32.f32 "
        "{%0,%1,%2,%3},{%4,%5,%6,%7},{%8,%9},{%0,%1,%2,%3};"
        : "+f"(c.x), "+f"(c.y), "+f"(c.z), "+f"(c.w)
        : "r"(a[0]), "r"(a[1]), "r"(a[2]), "r"(a[3]), "r"(b0), "r"(b1));
}
__device__ __forceinline__ void mma_bf16(float4& c, const uint32_t a[4],
                                         uint32_t b0, uint32_t b1) {
    asm("mma.sync.aligned.m16n8k16.row.col.f32.bf16.bf16.f32 "
        "{%0,%1,%2,%3},{%4,%5,%6,%7},{%8,%9},{%0,%1,%2,%3};"
        : "+f"(c.x), "+f"(c.y), "+f"(c.z), "+f"(c.w)
        : "r"(a[0]), "r"(a[1]), "r"(a[2]), "r"(a[3]), "r"(b0), "r"(b1));
}
__device__ __forceinline__ uint32_t bfpack(float a, float b) {
    uint32_t r; asm("cvt.rn.bf16x2.f32 %0, %1, %2;" : "=r"(r) : "f"(b), "f"(a)); return r;
}
__device__ __forceinline__ float bflowf(uint32_t v)  { return __uint_as_float(v << 16); }
__device__ __forceinline__ float bfhighf(uint32_t v) { return __uint_as_float(v & 0xFFFF0000u); }
__device__ __forceinline__ void cpa16(void* smem_dst, const void* gsrc) {
    uint32_t s = (uint32_t)__cvta_generic_to_shared(smem_dst);
    asm volatile("cp.async.cg.shared.global [%0], [%1], 16;" :: "r"(s), "l"(gsrc));
}
__device__ __forceinline__ void cpa_commit() {
    asm volatile("cp.async.commit_group;" ::: "memory");
}
template<int N>
__device__ __forceinline__ void cpa_wait() {
    asm volatile("cp.async.wait_group %0;" :: "n"(N) : "memory");
}

// ======================================================================
// Prep: Q encode (0..255), K encode (256..511), V transpose+split (512..767)
// ======================================================================
#define PREP_SMEM (2 * 64 * 264 * 2)
__global__ void __launch_bounds__(256) prep_kernel(
    const float* __restrict__ qin, const float* __restrict__ kin,
    const float* __restrict__ vin,
    const float* __restrict__ wq, const float* __restrict__ bq,
    const float* __restrict__ wk, const float* __restrict__ bk)
{
    extern __shared__ __nv_bfloat16 dynsm[];
    __shared__ float sw[NQV * DDIM];
    __shared__ float sb[NQV];
    const int bid = blockIdx.x;
    const int tid = threadIdx.x;

    if (bid >= 512) {   // ---- V transpose + bf16 split ----
        int vb = bid - 512;
        int bh = vb >> 2, sc0 = (vb & 3) * 256;
        int b = bh >> 3, h = bh & 7;
        const float4* vg = (const float4*)vin;
        __nv_bfloat16* smA = dynsm;
#pragma unroll
        for (int j = 0; j < 16; j++) {
            int i = tid + j * 256;
            int s = i >> 4, d4 = i & 15;
            float4 xv = vg[((size_t)((b * 1024 + sc0 + s) * 8 + h)) * 16 + d4];
            const float* px = &xv.x;
#pragma unroll
            for (int jj = 0; jj < 4; jj++) {
                int d = d4 * 4 + jj;
                float val = px[jj];
                __nv_bfloat16 hb = __float2bfloat16(val);
                float rr = val - __bfloat162float(hb);
                smA[d * 264 + s] = hb;
                smA[(64 + d) * 264 + s] = __float2bfloat16(rr);
            }
        }
        __syncthreads();
        __nv_bfloat16* dst = g_vT + (size_t)bh * 131072;
#pragma unroll
        for (int j = 0; j < 16; j++) {
            int i = tid + j * 256;
            int row = i >> 5, c = i & 31;
            float4 v4 = *(const float4*)&smA[row * 264 + c * 8];
            *(float4*)&dst[(size_t)row * 1024 + sc0 + c * 8] = v4;
        }
        return;
    }

    const int isK = (bid >= 256);
    const float* x = isK ? kin : qin;
    const float* w = isK ? wk : wq;
    const float* bias = isK ? bk : bq;
    if (tid < NQV * DDIM) sw[tid] = w[tid];
    if (tid < NQV) sb[tid] = bias[tid];
    __syncthreads();

    int n  = (bid & 255) * 256 + tid;
    int bh = n >> 10, loc = n & 1023;
    int b = bh >> 3, h = bh & 7;
    const float* xr = x + (size_t)((b * 1024 + loc) * HHN + h) * DDIM;

    float th[NQV];
#pragma unroll
    for (int j = 0; j < NQV; j++) th[j] = sb[j];
#pragma unroll 4
    for (int d = 0; d < DDIM; d += 4) {
        float4 xv = *(const float4*)(xr + d);
#pragma unroll
        for (int j = 0; j < NQV; j++) {
            th[j] += xv.x * sw[j * DDIM + d]     + xv.y * sw[j * DDIM + d + 1]
                   + xv.z * sw[j * DDIM + d + 2] + xv.w * sw[j * DDIM + d + 3];
        }
    }
#pragma unroll
    for (int j = 0; j < NQV; j++) th[j] = tanhf(th[j]) * PI_F;
    float bt[3];
#pragma unroll
    for (int p = 0; p < 3; p++) bt[p] = th[p] * th[p + 1];

    float co[16], si[16];
#pragma unroll
    for (int d = 0; d < 16; d++) {
        float a = 0.f;
        a += ((d >> 3) & 1) ? -th[0] : th[0];
        a += ((d >> 2) & 1) ? -th[1] : th[1];
        a += ((d >> 1) & 1) ? -th[2] : th[2];
        a += ( d       & 1) ? -th[3] : th[3];
        a += (((d >> 3) ^ (d >> 2)) & 1) ? -bt[0] : bt[0];
        a += (((d >> 2) ^ (d >> 1)) & 1) ? -bt[1] : bt[1];
        a += (((d >> 1) ^  d      ) & 1) ? -bt[2] : bt[2];
        sincosf(-0.5f * a, &si[d], &co[d]);
    }
    float re[16], im[16];
#pragma unroll
    for (int d = 0; d < 16; d++) { re[d] = co[d]; im[d] = si[d]; }
#pragma unroll
    for (int hs = 1; hs < 16; hs <<= 1) {
#pragma unroll
        for (int i = 0; i < 16; i++) {
            if ((i & hs) == 0) {
                int j2 = i | hs;
                float ar = re[i], ai = im[i], br = re[j2], bi = im[j2];
                re[i] = ar + br;  im[i] = ai + bi;
                re[j2] = ar - br; im[j2] = ai - bi;
            }
        }
    }

    float* o = (isK ? g_kB : g_qA) + (size_t)n * 96;
#pragma unroll
    for (int jg = 0; jg < 4; jg++) {
        float4 rhi, ihi, shi, rlo, ilo, slo;
        float* prh = &rhi.x; float* pih = &ihi.x; float* psh = &shi.x;
        float* prl = &rlo.x; float* pil = &ilo.x; float* psl = &slo.x;
#pragma unroll
        for (int jj = 0; jj < 4; jj++) {
            int d = jg * 4 + jj;
            float tr = re[d] * 0.0625f, ti = im[d] * 0.0625f;
            float vr = tr * co[d] - ti * si[d];
            float vi = tr * si[d] + ti * co[d];
            float vs = isK ? (vr - vi) : (vr + vi);
            float hi, lo;
            tsplit(vr, hi, lo); prh[jj] = hi; prl[jj] = lo;
            tsplit(vi, hi, lo); pih[jj] = hi; pil[jj] = lo;
            tsplit(vs, hi, lo); psh[jj] = hi; psl[jj] = lo;
        }
        float4* o4 = (float4*)o;
        o4[jg]      = rhi;  o4[4 + jg]  = ihi;  o4[8 + jg]  = shi;
        o4[12 + jg] = rlo;  o4[16 + jg] = ilo;  o4[20 + jg] = slo;
    }
}

// ======================================================================
// Fused attention, barrier-free per-warp pipelined staging, occ 2.
// Block = (bh, 16-l tile). smem: scores 64KB (swizzled) + 48KB warp buffers.
// ======================================================================
#define SMEM_BYTES ((16384 + 12288) * 4)    // 114688

__global__ void __launch_bounds__(256, 2) attn_fused(float* __restrict__ out)
{
    extern __shared__ uint32_t sm32[];
    uint32_t* scHi = sm32;                   // [16][512] swizzled bf16x2 hi pairs
    uint32_t* scLo = sm32 + 8192;            // [16][512] lo pairs
    __shared__ float sred[8][16];
    __shared__ float sinv[16];

    const int bh = blockIdx.y;
    const int l0 = blockIdx.x * 16;
    const int b = bh >> 3, h = bh & 7;
    const int tid = threadIdx.x;
    const int w = tid >> 5, lane = tid & 31;
    const int gr = lane >> 2, ctg = lane & 3;

    float* kb0 = (float*)(sm32 + 16384 + (w * 2) * 768);   // per-warp stage buffers
    float* kb1 = kb0 + 768;

    // resident tf32 Q fragments
    uint32_t ah[3][2][4], al[3][2][4];
    {
        const float* qa = g_qA + (size_t)bh * 98304 + (size_t)l0 * 96;
#pragma unroll
        for (int g = 0; g < 3; g++)
#pragma unroll
            for (int kk = 0; kk < 2; kk++) {
                int c0 = g * 16 + kk * 8 + ctg;
                ah[g][kk][0] = __float_as_uint(qa[gr * 96 + c0]);
                ah[g][kk][1] = __float_as_uint(qa[(gr + 8) * 96 + c0]);
                ah[g][kk][2] = __float_as_uint(qa[gr * 96 + c0 + 4]);
                ah[g][kk][3] = __float_as_uint(qa[(gr + 8) * 96 + c0 + 4]);
                al[g][kk][0] = __float_as_uint(qa[gr * 96 + 48 + c0]);
                al[g][kk][1] = __float_as_uint(qa[(gr + 8) * 96 + 48 + c0]);
                al[g][kk][2] = __float_as_uint(qa[gr * 96 + 48 + c0 + 4]);
                al[g][kk][3] = __float_as_uint(qa[(gr + 8) * 96 + 48 + c0 + 4]);
            }
    }

    // ---- phase A: per-warp pipelined scores ----
    const float* kg = g_kB + (size_t)bh * 98304;

    auto issueK = [&](int c, float* buf) {
        const float* src = kg + (size_t)(c * 64 + w * 8) * 96;
#pragma unroll
        for (int t = 0; t < 6; t++) {
            int fl = lane + 32 * t;
            int r = fl / 24, f = fl % 24;
            cpa16(buf + r * 96 + (((f ^ r)) << 2), src + r * 96 + f * 4);
        }
        cpa_commit();
    };

    float rs0 = 0.f, rs1 = 0.f;
    issueK(0, kb0);
    issueK(1, kb1);

#pragma unroll 1
    for (int c = 0; c < 16; c++) {
        if (c < 15) cpa_wait<1>(); else cpa_wait<0>();
        __syncwarp();
        float* buf = (c & 1) ? kb1 : kb0;

        // B fragments (swizzled): per (g,kk): hi f=F,F+1 ; lo f=F+12,F+13
        uint32_t bf[3][2][4];
        const float* bbase = buf + gr * 96;
#pragma unroll
        for (int g = 0; g < 3; g++)
#pragma unroll
            for (int kk = 0; kk < 2; kk++) {
                int F = g * 4 + kk * 2;
                bf[g][kk][0] = __float_as_uint(bbase[((F ^ gr) << 2) + ctg]);
                bf[g][kk][1] = __float_as_uint(bbase[(((F + 1) ^ gr) << 2) + ctg]);
                bf[g][kk][2] = __float_as_uint(bbase[(((F + 12) ^ gr) << 2) + ctg]);
                bf[g][kk][3] = __float_as_uint(bbase[(((F + 13) ^ gr) << 2) + ctg]);
            }
        __syncwarp();
        if (c < 14) issueK(c + 2, buf);

        float4 acc[3];
#pragma unroll
        for (int g = 0; g < 3; g++) acc[g] = make_float4(0.f, 0.f, 0.f, 0.f);
#pragma unroll
        for (int kk = 0; kk < 2; kk++)
#pragma unroll
            for (int g = 0; g < 3; g++) {
                mma_tf32(acc[g], ah[g][kk], bf[g][kk][0], bf[g][kk][1]);
                mma_tf32(acc[g], ah[g][kk], bf[g][kk][2], bf[g][kk][3]);
                mma_tf32(acc[g], al[g][kk], bf[g][kk][0], bf[g][kk][1]);
            }

        float4 c1 = acc[0], c2 = acc[1], c3 = acc[2];
        float fr, fi, p0, p1, p2, p3;
        fr = c1.x + c2.x; fi = c3.x - c1.x + c2.x; p0 = fr * fr + fi * fi;
        fr = c1.y + c2.y; fi = c3.y - c1.y + c2.y; p1 = fr * fr + fi * fi;
        fr = c1.z + c2.z; fi = c3.z - c1.z + c2.z; p2 = fr * fr + fi * fi;
        fr = c1.w + c2.w; fi = c3.w - c1.w + c2.w; p3 = fr * fr + fi * fi;

        int swz = (c * 32 + w * 4 + ctg) ^ (gr << 2);
        uint32_t h01 = bfpack(p0, p1);
        uint32_t h23 = bfpack(p2, p3);
        scHi[gr * 512 + swz] = h01;
        scHi[(gr + 8) * 512 + swz] = h23;
        scLo[gr * 512 + swz] = bfpack(p0 - bflowf(h01), p1 - bfhighf(h01));
        scLo[(gr + 8) * 512 + swz] = bfpack(p2 - bflowf(h23), p3 - bfhighf(h23));
        rs0 += p0 + p1; rs1 += p2 + p3;
    }

    // ---- rowsums ----
    rs0 += __shfl_xor_sync(0xFFFFFFFFu, rs0, 1);
    rs0 += __shfl_xor_sync(0xFFFFFFFFu, rs0, 2);
    rs1 += __shfl_xor_sync(0xFFFFFFFFu, rs1, 1);
    rs1 += __shfl_xor_sync(0xFFFFFFFFu, rs1, 2);
    if (ctg == 0) { sred[w][gr] = rs0; sred[w][gr + 8] = rs1; }
    __syncthreads();

    // ---- V pipeline prologue (overlaps weights write) ----
    const __nv_bfloat16* vt = g_vT + (size_t)bh * 131072;
    uint32_t* vb0 = sm32 + 16384 + (w * 2) * 768;
    uint32_t* vb1 = vb0 + 768;

    auto issueV = [&](int c, uint32_t* buf) {
#pragma unroll
        for (int t = 0; t < 4; t++) {
            int fl = lane + 32 * t;
            int rl = fl >> 3, f = fl & 7;
            int dg = w * 8 + (rl & 7) + ((rl & 8) ? 64 : 0);
            cpa16(buf + rl * 32 + ((f ^ (rl & 7)) << 2),
                  vt + (size_t)dg * 1024 + c * 64 + f * 8);
        }
        cpa_commit();
    };
    issueV(0, vb0);
    issueV(1, vb1);

    if (tid < 16) {
        float s = 0.f;
#pragma unroll
        for (int ww = 0; ww < 8; ww++) s += sred[ww][tid];
        sinv[tid] = 1.0f / (s + 1e-6f);
    }
    __syncthreads();

    // ---- phase B: single normalized weights pass ----
    {
        float2* wout = (float2*)(out + (size_t)CTX_ELEMS + ((size_t)bh * 1024 + l0) * 1024);
#pragma unroll 8
        for (int i = tid; i < 8192; i += 256) {
            int row = i >> 9, pr = i & 511;
            int idx = row * 512 + (pr ^ ((row & 7) << 2));
            uint32_t hv = scHi[idx];
            uint32_t lv = scLo[idx];
            float iv = sinv[row];
            float w0 = (bflowf(hv) + bflowf(lv)) * iv;
            float w1 = (bfhighf(hv) + bfhighf(lv)) * iv;
            wout[(size_t)row * 512 + pr] = make_float2(w0, w1);
        }
    }

    // ---- phase C: per-warp pipelined context ----
    float4 aHH = make_float4(0.f, 0.f, 0.f, 0.f);
    float4 aHL = make_float4(0.f, 0.f, 0.f, 0.f);
    float4 aLH = make_float4(0.f, 0.f, 0.f, 0.f);

#pragma unroll 1
    for (int c = 0; c < 16; c++) {
        if (c < 15) cpa_wait<1>(); else cpa_wait<0>();
        __syncwarp();
        uint32_t* buf = (c & 1) ? vb1 : vb0;

        // B fragments for 4 ksteps
        uint32_t vb[4][4];
        const uint32_t* vh = buf + gr * 32;
        const uint32_t* vl = buf + (8 + gr) * 32;
#pragma unroll
        for (int kk = 0; kk < 4; kk++) {
            int F = kk * 2;
            vb[kk][0] = vh[((F ^ gr) << 2) + ctg];
            vb[kk][1] = vh[(((F + 1) ^ gr) << 2) + ctg];
            vb[kk][2] = vl[((F ^ gr) << 2) + ctg];
            vb[kk][3] = vl[(((F + 1) ^ gr) << 2) + ctg];
        }
        __syncwarp();
        if (c < 14) issueV(c + 2, buf);

#pragma unroll
        for (int kk = 0; kk < 4; kk++) {
            int p0i = (c * 32 + kk * 8 + ctg) ^ (gr << 2);
            int p1i = (c * 32 + kk * 8 + 4 + ctg) ^ (gr << 2);
            uint32_t aH[4], aL[4];
            aH[0] = scHi[gr * 512 + p0i];
            aH[1] = scHi[(gr + 8) * 512 + p0i];
            aH[2] = scHi[gr * 512 + p1i];
            aH[3] = scHi[(gr + 8) * 512 + p1i];
            aL[0] = scLo[gr * 512 + p0i];
            aL[1] = scLo[(gr + 8) * 512 + p0i];
            aL[2] = scLo[gr * 512 + p1i];
            aL[3] = scLo[(gr + 8) * 512 + p1i];

            mma_bf16(aHH, aH, vb[kk][0], vb[kk][1]);
            mma_bf16(aHL, aH, vb[kk][2], vb[kk][3]);
            mma_bf16(aLH, aL, vb[kk][0], vb[kk][1]);
        }
    }

    {
        float4 cc = make_float4(aHH.x + aHL.x + aLH.x, aHH.y + aHL.y + aLH.y,
                                aHH.z + aHL.z + aLH.z, aHH.w + aHL.w + aLH.w);
        float ivt = sinv[gr], ivb = sinv[gr + 8];
        int lt = l0 + gr, lb = lt + 8;
        int d = w * 8 + 2 * ctg;
        *(float2*)&out[((size_t)((b * 1024 + lt) * 8 + h)) * 64 + d]
            = make_float2(cc.x * ivt, cc.y * ivt);
        *(float2*)&out[((size_t)((b * 1024 + lb) * 8 + h)) * 64 + d]
            = make_float2(cc.z * ivb, cc.w * ivb);
    }
}

// ======================================================================
extern "C" void kernel_launch(void* const* d_in, const int* in_sizes, int n_in,
                              void* d_out, int out_size)
{
    (void)in_sizes; (void)n_in; (void)out_size;
    const float* q  = (const float*)d_in[0];
    const float* k  = (const float*)d_in[1];
    const float* v  = (const float*)d_in[2];
    const float* wq = (const float*)d_in[3];
    const float* bq = (const float*)d_in[4];
    const float* wk = (const float*)d_in[5];
    const float* bk = (const float*)d_in[6];
    float* out = (float*)d_out;

    cudaFuncSetAttribute(prep_kernel, cudaFuncAttributeMaxDynamicSharedMemorySize, PREP_SMEM);
    cudaFuncSetAttribute(attn_fused,  cudaFuncAttributeMaxDynamicSharedMemorySize, SMEM_BYTES);

    prep_kernel<<<768, 256, PREP_SMEM>>>(q, k, v, wq, bq, wk, bk);
    attn_fused<<<dim3(64, BHN), 256, SMEM_BYTES>>>(out);
}

// round 7
// speedup vs baseline: 2.5966x; 1.4288x over previous
#include <cuda_runtime.h>
#include <cuda_bf16.h>
#include <math.h>
#include <stdint.h>

typedef unsigned long long u64;

#define BB   8
#define LL   1024
#define HHN  8
#define NQV  4
#define BHN  (BB*HHN)
#define CTX_ELEMS (BB*LL*HHN*64)
#define PI_F 3.14159274101257324f

// Karatsuba bf16-split Q/K: [bh][pos][96 bf16] =
//   [r_hi16 | i_hi16 | s_hi16 | r_lo16 | i_lo16 | s_lo16]   (192 B/pos)
__device__ __nv_bfloat16 g_qA[(size_t)BHN * 1024 * 96];
__device__ __nv_bfloat16 g_kB[(size_t)BHN * 1024 * 96];
// V interleaved: [bh][d 0..63][s-pair 0..511] u64 = (hi bf16x2 | lo bf16x2 << 32)
__device__ u64 g_vTi[(size_t)BHN * 64 * 512];

// ---------------- helpers ----------------
__device__ __forceinline__ void mma_bf16(float4& c, const uint32_t a[4],
                                         uint32_t b0, uint32_t b1) {
    asm("mma.sync.aligned.m16n8k16.row.col.f32.bf16.bf16.f32 "
        "{%0,%1,%2,%3},{%4,%5,%6,%7},{%8,%9},{%0,%1,%2,%3};"
        : "+f"(c.x), "+f"(c.y), "+f"(c.z), "+f"(c.w)
        : "r"(a[0]), "r"(a[1]), "r"(a[2]), "r"(a[3]), "r"(b0), "r"(b1));
}
__device__ __forceinline__ uint32_t bfpack(float a, float b) {   // a->low, b->high
    uint32_t r; asm("cvt.rn.bf16x2.f32 %0, %1, %2;" : "=r"(r) : "f"(b), "f"(a)); return r;
}
__device__ __forceinline__ float bflowf(uint32_t v)  { return __uint_as_float(v << 16); }
__device__ __forceinline__ float bfhighf(uint32_t v) { return __uint_as_float(v & 0xFFFF0000u); }
__device__ __forceinline__ void cpa16(void* smem_dst, const void* gsrc) {
    uint32_t s = (uint32_t)__cvta_generic_to_shared(smem_dst);
    asm volatile("cp.async.cg.shared.global [%0], [%1], 16;" :: "r"(s), "l"(gsrc));
}
__device__ __forceinline__ void cpa_commit() {
    asm volatile("cp.async.commit_group;" ::: "memory");
}
template<int N>
__device__ __forceinline__ void cpa_wait() {
    asm volatile("cp.async.wait_group %0;" :: "n"(N) : "memory");
}

// ======================================================================
// Prep: Q encode (0..255), K encode (256..511), V interleave (512..767)
// ======================================================================
#define PREP_SMEM (128 * 264 * 2)
__global__ void __launch_bounds__(256) prep_kernel(
    const float* __restrict__ qin, const float* __restrict__ kin,
    const float* __restrict__ vin,
    const float* __restrict__ wq, const float* __restrict__ bq,
    const float* __restrict__ wk, const float* __restrict__ bk)
{
    extern __shared__ __nv_bfloat16 smA[];
    __shared__ float sw[NQV * 64];
    __shared__ float sb[NQV];
    const int bid = blockIdx.x;
    const int tid = threadIdx.x;

    if (bid >= 512) {   // ---- V transpose + bf16 split + interleave ----
        int vb = bid - 512;
        int bh = vb >> 2, sc0 = (vb & 3) * 256;
        int b = bh >> 3, h = bh & 7;
        const float4* vg = (const float4*)vin;
#pragma unroll
        for (int j = 0; j < 16; j++) {
            int i = tid + j * 256;
            int s = i >> 4, d4 = i & 15;
            float4 xv = vg[((size_t)((b * 1024 + sc0 + s) * 8 + h)) * 16 + d4];
            const float* px = &xv.x;
#pragma unroll
            for (int jj = 0; jj < 4; jj++) {
                int d = d4 * 4 + jj;
                float val = px[jj];
                __nv_bfloat16 hb = __float2bfloat16(val);
                smA[d * 264 + s] = hb;
                smA[(64 + d) * 264 + s] = __float2bfloat16(val - __bfloat162float(hb));
            }
        }
        __syncthreads();
        u64* dst = g_vTi + (size_t)bh * 32768;
#pragma unroll
        for (int j = 0; j < 8; j++) {
            int i = tid + j * 256;
            int row = i >> 5, cc = i & 31;
            uint4 hv = *(const uint4*)&smA[row * 264 + cc * 8];
            uint4 lv = *(const uint4*)&smA[(64 + row) * 264 + cc * 8];
            size_t di = (size_t)row * 512 + (sc0 >> 1) + cc * 4;
            *(ulonglong2*)&dst[di] =
                make_ulonglong2(hv.x | ((u64)lv.x << 32), hv.y | ((u64)lv.y << 32));
            *(ulonglong2*)&dst[di + 2] =
                make_ulonglong2(hv.z | ((u64)lv.z << 32), hv.w | ((u64)lv.w << 32));
        }
        return;
    }

    const int isK = (bid >= 256);
    const float* x = isK ? kin : qin;
    const float* w = isK ? wk : wq;
    const float* bias = isK ? bk : bq;
    if (tid < NQV * 64) sw[tid] = w[tid];
    if (tid < NQV) sb[tid] = bias[tid];
    __syncthreads();

    int n  = (bid & 255) * 256 + tid;
    int bh = n >> 10, loc = n & 1023;
    int b = bh >> 3, h = bh & 7;
    const float* xr = x + (size_t)((b * 1024 + loc) * HHN + h) * 64;

    float th[NQV];
#pragma unroll
    for (int j = 0; j < NQV; j++) th[j] = sb[j];
#pragma unroll 4
    for (int d = 0; d < 64; d += 4) {
        float4 xv = *(const float4*)(xr + d);
#pragma unroll
        for (int j = 0; j < NQV; j++) {
            th[j] += xv.x * sw[j * 64 + d]     + xv.y * sw[j * 64 + d + 1]
                   + xv.z * sw[j * 64 + d + 2] + xv.w * sw[j * 64 + d + 3];
        }
    }
#pragma unroll
    for (int j = 0; j < NQV; j++) th[j] = tanhf(th[j]) * PI_F;
    float bt[3];
#pragma unroll
    for (int p = 0; p < 3; p++) bt[p] = th[p] * th[p + 1];

    float co[16], si[16];
#pragma unroll
    for (int d = 0; d < 16; d++) {
        float a = 0.f;
        a += ((d >> 3) & 1) ? -th[0] : th[0];
        a += ((d >> 2) & 1) ? -th[1] : th[1];
        a += ((d >> 1) & 1) ? -th[2] : th[2];
        a += ( d       & 1) ? -th[3] : th[3];
        a += (((d >> 3) ^ (d >> 2)) & 1) ? -bt[0] : bt[0];
        a += (((d >> 2) ^ (d >> 1)) & 1) ? -bt[1] : bt[1];
        a += (((d >> 1) ^  d      ) & 1) ? -bt[2] : bt[2];
        sincosf(-0.5f * a, &si[d], &co[d]);
    }
    float re[16], im[16];
#pragma unroll
    for (int d = 0; d < 16; d++) { re[d] = co[d]; im[d] = si[d]; }
#pragma unroll
    for (int hs = 1; hs < 16; hs <<= 1) {
#pragma unroll
        for (int i = 0; i < 16; i++) {
            if ((i & hs) == 0) {
                int j2 = i | hs;
                float ar = re[i], ai = im[i], br = re[j2], bi = im[j2];
                re[i] = ar + br;  im[i] = ai + bi;
                re[j2] = ar - br; im[j2] = ai - bi;
            }
        }
    }

    float fr[16], fi[16], fs[16];
#pragma unroll
    for (int d = 0; d < 16; d++) {
        float tr = re[d] * 0.0625f, ti = im[d] * 0.0625f;
        fr[d] = tr * co[d] - ti * si[d];
        fi[d] = tr * si[d] + ti * co[d];
        fs[d] = isK ? (fr[d] - fi[d]) : (fr[d] + fi[d]);
    }

    uint32_t uw[48];
#pragma unroll
    for (int j = 0; j < 8; j++) {
        uint32_t hp;
        hp = bfpack(fr[2*j], fr[2*j+1]);
        uw[j] = hp;
        uw[24 + j] = bfpack(fr[2*j] - bflowf(hp), fr[2*j+1] - bfhighf(hp));
        hp = bfpack(fi[2*j], fi[2*j+1]);
        uw[8 + j] = hp;
        uw[32 + j] = bfpack(fi[2*j] - bflowf(hp), fi[2*j+1] - bfhighf(hp));
        hp = bfpack(fs[2*j], fs[2*j+1]);
        uw[16 + j] = hp;
        uw[40 + j] = bfpack(fs[2*j] - bflowf(hp), fs[2*j+1] - bfhighf(hp));
    }
    uint4* o4 = (uint4*)((isK ? g_kB : g_qA) + (size_t)n * 96);
#pragma unroll
    for (int q = 0; q < 12; q++)
        o4[q] = make_uint4(uw[4*q], uw[4*q+1], uw[4*q+2], uw[4*q+3]);
}

// ======================================================================
// Fused attention, bf16 Karatsuba, u64-interleaved operands, occ 2.
// Block = (bh, 16-l tile). smem: scores 66048 B + 8 x 4608 B warp buffers.
// ======================================================================
#define SC_STRIDE 516                       // u64 per score row (conflict-free)
#define SC_U64 (16 * SC_STRIDE)             // 8256
#define WARP_U64 576                        // 4608 B per warp (2 stages)
#define SMEM_BYTES ((SC_U64 + 8 * WARP_U64) * 8)   // 102912

__global__ void __launch_bounds__(256, 2) attn_fused(float* __restrict__ out)
{
    extern __shared__ u64 sm64[];
    u64* scores = sm64;                      // [16][516]
    __shared__ float sred[8][16];
    __shared__ float sinv[16];

    const int bh = blockIdx.y;
    const int l0 = blockIdx.x * 16;
    const int b = bh >> 3, h = bh & 7;
    const int tid = threadIdx.x;
    const int w = tid >> 5, lane = tid & 31;
    const int gr = lane >> 2, ctg = lane & 3;

    // resident bf16 Q fragments: 3 Karatsuba gemms, hi+lo
    uint32_t Ah[3][4], Al[3][4];
    {
        const uint32_t* qa = (const uint32_t*)g_qA + (size_t)bh * 49152 + (size_t)l0 * 48;
#pragma unroll
        for (int g = 0; g < 3; g++) {
            Ah[g][0] = qa[gr * 48 + g * 8 + ctg];
            Ah[g][1] = qa[(gr + 8) * 48 + g * 8 + ctg];
            Ah[g][2] = qa[gr * 48 + g * 8 + 4 + ctg];
            Ah[g][3] = qa[(gr + 8) * 48 + g * 8 + 4 + ctg];
            Al[g][0] = qa[gr * 48 + 24 + g * 8 + ctg];
            Al[g][1] = qa[(gr + 8) * 48 + 24 + g * 8 + ctg];
            Al[g][2] = qa[gr * 48 + 24 + g * 8 + 4 + ctg];
            Al[g][3] = qa[(gr + 8) * 48 + 24 + g * 8 + 4 + ctg];
        }
    }

    // ---- phase A: per-warp pipelined scores ----
    const __nv_bfloat16* kg = g_kB + (size_t)bh * 98304;
    uint32_t* kb0 = (uint32_t*)(sm64 + SC_U64 + w * WARP_U64);
    uint32_t* kb1 = kb0 + 576;               // second 2304 B half

    auto issueK = [&](int c, uint32_t* buf) {
        const __nv_bfloat16* src = kg + (size_t)(c * 64 + w * 8) * 96;
#pragma unroll
        for (int t = 0; t < 3; t++) {
            int fl = lane + 32 * t;
            int r = fl / 12, f = fl % 12;
            cpa16(buf + r * 52 + f * 4, src + r * 96 + f * 8);
        }
        cpa_commit();
    };

    float rs0 = 0.f, rs1 = 0.f;
    issueK(0, kb0);
    issueK(1, kb1);

#pragma unroll 1
    for (int c = 0; c < 16; c++) {
        if (c < 15) cpa_wait<1>(); else cpa_wait<0>();
        __syncwarp();
        uint32_t* buf = (c & 1) ? kb1 : kb0;

        uint32_t B[3][4];
        const uint32_t* bb = buf + gr * 52;
#pragma unroll
        for (int g = 0; g < 3; g++) {
            B[g][0] = bb[g * 8 + ctg];
            B[g][1] = bb[g * 8 + 4 + ctg];
            B[g][2] = bb[24 + g * 8 + ctg];
            B[g][3] = bb[24 + g * 8 + 4 + ctg];
        }
        __syncwarp();
        if (c < 14) issueK(c + 2, buf);

        float4 acc[3];
#pragma unroll
        for (int g = 0; g < 3; g++) acc[g] = make_float4(0.f, 0.f, 0.f, 0.f);
#pragma unroll
        for (int g = 0; g < 3; g++) {
            mma_bf16(acc[g], Ah[g], B[g][0], B[g][1]);
            mma_bf16(acc[g], Ah[g], B[g][2], B[g][3]);
            mma_bf16(acc[g], Al[g], B[g][0], B[g][1]);
        }

        float4 c1 = acc[0], c2 = acc[1], c3 = acc[2];
        float fr, fi, p0, p1, p2, p3;
        fr = c1.x + c2.x; fi = c3.x - c1.x + c2.x; p0 = fr * fr + fi * fi;
        fr = c1.y + c2.y; fi = c3.y - c1.y + c2.y; p1 = fr * fr + fi * fi;
        fr = c1.z + c2.z; fi = c3.z - c1.z + c2.z; p2 = fr * fr + fi * fi;
        fr = c1.w + c2.w; fi = c3.w - c1.w + c2.w; p3 = fr * fr + fi * fi;

        int idx = c * 32 + w * 4 + ctg;
        uint32_t h01 = bfpack(p0, p1);
        uint32_t h23 = bfpack(p2, p3);
        uint32_t l01 = bfpack(p0 - bflowf(h01), p1 - bfhighf(h01));
        uint32_t l23 = bfpack(p2 - bflowf(h23), p3 - bfhighf(h23));
        scores[gr * SC_STRIDE + idx] = (u64)h01 | ((u64)l01 << 32);
        scores[(gr + 8) * SC_STRIDE + idx] = (u64)h23 | ((u64)l23 << 32);
        rs0 += p0 + p1; rs1 += p2 + p3;
    }

    // ---- rowsums ----
    rs0 += __shfl_xor_sync(0xFFFFFFFFu, rs0, 1);
    rs0 += __shfl_xor_sync(0xFFFFFFFFu, rs0, 2);
    rs1 += __shfl_xor_sync(0xFFFFFFFFu, rs1, 1);
    rs1 += __shfl_xor_sync(0xFFFFFFFFu, rs1, 2);
    if (ctg == 0) { sred[w][gr] = rs0; sred[w][gr + 8] = rs1; }
    __syncthreads();

    // ---- V pipeline prologue (overlaps weights write) ----
    const u64* vt = g_vTi + (size_t)bh * 32768;
    u64* vb0 = sm64 + SC_U64 + w * WARP_U64;
    u64* vb1 = vb0 + 288;

    auto issueV = [&](int c, u64* buf) {
#pragma unroll
        for (int t = 0; t < 4; t++) {
            int fl = lane + 32 * t;
            int r = fl >> 4, f = fl & 15;
            cpa16(buf + r * 36 + f * 2, vt + (size_t)(w * 8 + r) * 512 + c * 32 + f * 2);
        }
        cpa_commit();
    };
    issueV(0, vb0);
    issueV(1, vb1);

    if (tid < 16) {
        float s = 0.f;
#pragma unroll
        for (int ww = 0; ww < 8; ww++) s += sred[ww][tid];
        sinv[tid] = 1.0f / (s + 1e-6f);
    }
    __syncthreads();

    // ---- phase B: single normalized weights pass ----
    {
        float2* wout = (float2*)(out + (size_t)CTX_ELEMS + ((size_t)bh * 1024 + l0) * 1024);
#pragma unroll 8
        for (int i = tid; i < 8192; i += 256) {
            int row = i >> 9, pr = i & 511;
            u64 v = scores[row * SC_STRIDE + pr];
            uint32_t hv = (uint32_t)v, lv = (uint32_t)(v >> 32);
            float iv = sinv[row];
            wout[(size_t)row * 512 + pr] =
                make_float2((bflowf(hv) + bflowf(lv)) * iv,
                            (bfhighf(hv) + bfhighf(lv)) * iv);
        }
    }

    // ---- phase C: per-warp pipelined context (warp = d-octet) ----
    float4 aHH = make_float4(0.f, 0.f, 0.f, 0.f);
    float4 aHL = make_float4(0.f, 0.f, 0.f, 0.f);
    float4 aLH = make_float4(0.f, 0.f, 0.f, 0.f);

#pragma unroll 1
    for (int c = 0; c < 16; c++) {
        if (c < 15) cpa_wait<1>(); else cpa_wait<0>();
        __syncwarp();
        u64* buf = (c & 1) ? vb1 : vb0;

        u64 vv[4][2];
#pragma unroll
        for (int kk = 0; kk < 4; kk++) {
            vv[kk][0] = buf[gr * 36 + kk * 8 + ctg];
            vv[kk][1] = buf[gr * 36 + kk * 8 + 4 + ctg];
        }
        __syncwarp();
        if (c < 14) issueV(c + 2, buf);

#pragma unroll
        for (int kk = 0; kk < 4; kk++) {
            int base = c * 32 + kk * 8;
            u64 s0 = scores[gr * SC_STRIDE + base + ctg];
            u64 s1 = scores[(gr + 8) * SC_STRIDE + base + ctg];
            u64 s2 = scores[gr * SC_STRIDE + base + 4 + ctg];
            u64 s3 = scores[(gr + 8) * SC_STRIDE + base + 4 + ctg];
            uint32_t aH[4] = {(uint32_t)s0, (uint32_t)s1, (uint32_t)s2, (uint32_t)s3};
            uint32_t aL[4] = {(uint32_t)(s0 >> 32), (uint32_t)(s1 >> 32),
                              (uint32_t)(s2 >> 32), (uint32_t)(s3 >> 32)};
            uint32_t bh0 = (uint32_t)vv[kk][0], bh1 = (uint32_t)vv[kk][1];
            uint32_t bl0 = (uint32_t)(vv[kk][0] >> 32), bl1 = (uint32_t)(vv[kk][1] >> 32);

            mma_bf16(aHH, aH, bh0, bh1);
            mma_bf16(aHL, aH, bl0, bl1);
            mma_bf16(aLH, aL, bh0, bh1);
        }
    }

    {
        float4 cc = make_float4(aHH.x + aHL.x + aLH.x, aHH.y + aHL.y + aLH.y,
                                aHH.z + aHL.z + aLH.z, aHH.w + aHL.w + aLH.w);
        float ivt = sinv[gr], ivb = sinv[gr + 8];
        int lt = l0 + gr, lb = lt + 8;
        int d = w * 8 + 2 * ctg;
        *(float2*)&out[((size_t)((b * 1024 + lt) * 8 + h)) * 64 + d]
            = make_float2(cc.x * ivt, cc.y * ivt);
        *(float2*)&out[((size_t)((b * 1024 + lb) * 8 + h)) * 64 + d]
            = make_float2(cc.z * ivb, cc.w * ivb);
    }
}

// ======================================================================
extern "C" void kernel_launch(void* const* d_in, const int* in_sizes, int n_in,
                              void* d_out, int out_size)
{
    (void)in_sizes; (void)n_in; (void)out_size;
    const float* q  = (const float*)d_in[0];
    const float* k  = (const float*)d_in[1];
    const float* v  = (const float*)d_in[2];
    const float* wq = (const float*)d_in[3];
    const float* bq = (const float*)d_in[4];
    const float* wk = (const float*)d_in[5];
    const float* bk = (const float*)d_in[6];
    float* out = (float*)d_out;

    cudaFuncSetAttribute(prep_kernel, cudaFuncAttributeMaxDynamicSharedMemorySize, PREP_SMEM);
    cudaFuncSetAttribute(attn_fused,  cudaFuncAttributeMaxDynamicSharedMemorySize, SMEM_BYTES);

    prep_kernel<<<768, 256, PREP_SMEM>>>(q, k, v, wq, bq, wk, bk);
    attn_fused<<<dim3(64, BHN), 256, SMEM_BYTES>>>(out);
}